// round 8
// baseline (speedup 1.0000x reference)
#include <cuda_runtime.h>
#include <cstdint>

// Forward 5/3 lifting wavelet, 2D separable, fused tile kernel.
// x: (8, 32, 512, 512) f32 -> out: (8, 128, 256, 256) f32
// out channels: [LL(0:32) | LH(32:64) | HL(64:96) | HH(96:128)]
//
//   d[i] = odd[i] - 0.5*(even[il] + even[ir]), il=(i==0)?1:i-1, ir=(i==255)?254:i+1
//   s[i] = even[i] + 0.25*(d[il] + d[ir])     (same reflected indices)
//
// R=8 rows/strip, 256-thread CTAs, 22-row smem tile (the unused halo row
// 2*r0-3 is skipped) = 45056B -> 5 CTAs/SM, 40 warps/SM.

static constexpr int H = 512;
static constexpr int Wd = 512;
static constexpr int R = 8;               // output rows per strip
static constexpr int NSTRIP = 256 / R;    // 32
static constexpr int NBC = 8 * 32;        // 256 images
static constexpr int SMEM_BYTES = 22 * Wd * 4; // 45056

static constexpr unsigned FULL = 0xffffffffu;

__device__ __forceinline__ float2 f2_add(float2 a, float2 b) {
    return make_float2(a.x + b.x, a.y + b.y);
}
__device__ __forceinline__ float2 f2_fma(float k, float2 a, float2 b) {
    return make_float2(fmaf(k, a.x, b.x), fmaf(k, a.y, b.y));
}

__global__ __launch_bounds__(256, 5)
void lwt53_fused_kernel(const float* __restrict__ x, float* __restrict__ out) {
    extern __shared__ float A[];   // [22 slots][512]; per row: s in [0,256), d in [256,512)

    const int blk   = blockIdx.x;
    const int strip = blk & (NSTRIP - 1);
    const int bc    = blk >> 5;
    const int r0    = strip * R;

    // slot -> gmem input row:
    //   r0==0 : m = slot            (slots 0..18)
    //   r0>0  : m = (slot==0) ? 2*r0-4 : 2*r0-3+slot   (skips row 2*r0-3)
    const int NS = (r0 == 0 || r0 == 248) ? 19 : 22;

    const float* __restrict__ xim = x + (size_t)bc * (H * Wd);

    const int tid  = threadIdx.x;
    const int warp = tid >> 5;
    const int lane = tid & 31;

    // ================= Phase A: row lifting in registers =================
    for (int s = warp; s < NS; s += 8) {
        const int m = (r0 == 0) ? s : ((s == 0) ? (2 * r0 - 4) : (2 * r0 - 3 + s));
        const float4* __restrict__ xr =
            reinterpret_cast<const float4*>(xim + (unsigned)m * Wd);
        float eA[4], oA[4], eB[4], oB[4];
        #pragma unroll
        for (int j = 0; j < 4; j++) {
            const float4 v = xr[32 * j + lane];
            eA[j] = v.x; oA[j] = v.y; eB[j] = v.z; oB[j] = v.w;
        }

        float dA[4], dB[4];
        #pragma unroll
        for (int j = 0; j < 4; j++) {
            float up = __shfl_up_sync(FULL, eB[j], 1);
            float cp = __shfl_sync(FULL, (j > 0) ? eB[j - 1] : eB[j], 31);
            float Eprev = (lane == 0) ? ((j == 0) ? eB[0] : cp) : up;   // refl i=0
            float dn = __shfl_down_sync(FULL, eA[j], 1);
            float cn = __shfl_sync(FULL, (j < 3) ? eA[j + 1] : eA[j], 0);
            float Enext = (lane == 31) ? ((j == 3) ? eA[3] : cn) : dn;  // refl i=255
            dA[j] = oA[j] - 0.5f * (Eprev + eB[j]);
            dB[j] = oB[j] - 0.5f * (eA[j] + Enext);
        }

        float* Arow = A + s * Wd;
        float2* __restrict__ srow = reinterpret_cast<float2*>(Arow);
        float2* __restrict__ drow = reinterpret_cast<float2*>(Arow + 256);
        #pragma unroll
        for (int j = 0; j < 4; j++) {
            float up = __shfl_up_sync(FULL, dB[j], 1);
            float cp = __shfl_sync(FULL, (j > 0) ? dB[j - 1] : dB[j], 31);
            float Dprev = (lane == 0) ? ((j == 0) ? dB[0] : cp) : up;
            float dn = __shfl_down_sync(FULL, dA[j], 1);
            float cn = __shfl_sync(FULL, (j < 3) ? dA[j + 1] : dA[j], 0);
            float Dnext = (lane == 31) ? ((j == 3) ? dA[3] : cn) : dn;
            float sA = eA[j] + 0.25f * (Dprev + dB[j]);
            float sB = eB[j] + 0.25f * (dA[j] + Dnext);
            srow[32 * j + lane] = make_float2(sA, sB);
            drow[32 * j + lane] = make_float2(dA[j], dB[j]);
        }
    }
    __syncthreads();

    // ============ Phase B: column lifting, 3-term sliding window ============
    // Thread owns a float2 column pair. t<128: s-columns (-> LL/LH);
    // t>=128: d-columns (-> HL/HH). Same verified recurrence as R7, with the
    // 22-slot row mapping:
    //   E[j] -> slot 2*(j-r0)+3 (r0>0; E[r0-2] -> slot 0), or 2*j (r0==0)
    //   O[j] -> slot 2*(j-r0)+4 (r0>0), or 2*j+1 (r0==0)
    {
        const int t  = tid;
        const unsigned cc = (t & 127) * 2;              // coefficient column (even)
        const unsigned sb = (t < 128) ? 0u : 256u;      // smem half offset

        const int eOff = r0 ? (3 - 2 * r0) : 0;         // slotE(j) = 2*j + eOff (j>=r0-1)
        const int oOff = r0 ? (4 - 2 * r0) : 1;         // slotO(j) = 2*j + oOff

        auto ldE = [&](int slot) -> float2 {
            return *reinterpret_cast<const float2*>(A + (unsigned)slot * Wd + sb + cc);
        };

        // Output addressing (32-bit offsets)
        const int b = bc >> 5;
        const int c = bc & 31;
        float* __restrict__ base = out + ((size_t)(b * 128 + c)) * 65536u;
        float* __restrict__ sOut = base + ((t < 128) ? 0u : 64u * 65536u);
        float* __restrict__ dOut = base + ((t < 128) ? 32u * 65536u : 96u * 65536u);

        const int jstart = (r0 == 0)   ? 0   : (r0 - 1);
        const int jend   = (r0 == 248) ? 255 : (r0 + R);

        float2 eA = ldE((r0 == 0) ? 2 : 0);             // E[refl(jstart-1)]
        float2 eB = ldE(2 * jstart + eOff);             // E[jstart]
        float2 Dm1 = make_float2(0.f, 0.f), Dm2 = make_float2(0.f, 0.f);

        for (int j = jstart; j <= jend; ++j) {
            const int jp = (j >= 255) ? 254 : (j + 1);
            const float2 eC = ldE(2 * jp + eOff);
            const float2 O  = ldE(2 * j + oOff);

            const float2 D = f2_fma(-0.5f, f2_add(eA, eC), O);

            if (j >= r0 && j <= r0 + R - 1) {
                const unsigned o = (unsigned)j * 256u + cc;
                __stcs(reinterpret_cast<float2*>(dOut + o), D);
            }
            if (j >= r0 + 1) {
                const float2 DA = (r0 == 0 && j == 1) ? D : Dm2;  // S[0] reflect
                const float2 S = f2_fma(0.25f, f2_add(DA, D), eA);
                const unsigned o = (unsigned)(j - 1) * 256u + cc;
                __stcs(reinterpret_cast<float2*>(sOut + o), S);
            }

            Dm2 = Dm1; Dm1 = D;
            eA = eB; eB = eC;
        }

        if (r0 == 248) {
            // S[255] = E[255] + 0.25*(2*D[254]); after final shift eA=E[255], Dm2=D[254]
            const float2 S = f2_fma(0.5f, Dm2, eA);
            const unsigned o = 255u * 256u + cc;
            __stcs(reinterpret_cast<float2*>(sOut + o), S);
        }
    }
}

extern "C" void kernel_launch(void* const* d_in, const int* in_sizes, int n_in,
                              void* d_out, int out_size) {
    const float* x = (const float*)d_in[0];
    float* out = (float*)d_out;
    (void)in_sizes; (void)n_in; (void)out_size;

    static bool attr_set = false;
    if (!attr_set) {
        cudaFuncSetAttribute(lwt53_fused_kernel,
                             cudaFuncAttributeMaxDynamicSharedMemorySize, SMEM_BYTES);
        attr_set = true;
    }

    dim3 grid(NBC * NSTRIP);   // 8192
    dim3 block(256);
    lwt53_fused_kernel<<<grid, block, SMEM_BYTES>>>(x, out);
}

// round 9
// speedup vs baseline: 1.1110x; 1.1110x over previous
#include <cuda_runtime.h>
#include <cstdint>

// Forward 5/3 lifting wavelet, 2D separable, fused tile kernel.
// x: (8, 32, 512, 512) f32 -> out: (8, 128, 256, 256) f32
// out channels: [LL(0:32) | LH(32:64) | HL(64:96) | HH(96:128)]
//
//   d[i] = odd[i] - 0.5*(even[il] + even[ir]), il=(i==0)?1:i-1, ir=(i==255)?254:i+1
//   s[i] = even[i] + 0.25*(d[il] + d[ir])     (same reflected indices)
//
// R=8 output rows per strip, 256-thread CTAs, 47KB smem -> 4 CTAs/SM (the
// verified sweet spot: 4 independent load->barrier->store machines per SM,
// 40KB of L1D left for halo-row reuse). Slot 1 (input row 2*r0-3) is dead
// for interior strips and is skipped in Phase A (no slot remap).

static constexpr int H = 512;
static constexpr int Wd = 512;
static constexpr int R = 8;               // output rows per strip
static constexpr int NSTRIP = 256 / R;    // 32
static constexpr int NBC = 8 * 32;        // 256 images
static constexpr int MAXROWS = 2 * R + 7; // 23
static constexpr int SMEM_BYTES = MAXROWS * Wd * 4; // 47104

static constexpr unsigned FULL = 0xffffffffu;

__device__ __forceinline__ float2 f2_add(float2 a, float2 b) {
    return make_float2(a.x + b.x, a.y + b.y);
}
__device__ __forceinline__ float2 f2_fma(float k, float2 a, float2 b) {
    return make_float2(fmaf(k, a.x, b.x), fmaf(k, a.y, b.y));
}

__global__ __launch_bounds__(256, 4)
void lwt53_fused_kernel(const float* __restrict__ x, float* __restrict__ out) {
    extern __shared__ float A[];   // [nrows][512]; per row: s in [0,256), d in [256,512)

    const int blk   = blockIdx.x;
    const int strip = blk & (NSTRIP - 1);
    const int bc    = blk >> 5;            // log2(NSTRIP)=5
    const int r0    = strip * R;

    const int mlo   = max(0, 2 * r0 - 4);
    const int mhi   = min(H - 1, 2 * r0 + 2 * R + 2);
    const int nrows = mhi - mlo + 1;

    const float* __restrict__ xim = x + (size_t)bc * (H * Wd) + (size_t)mlo * Wd;

    const int tid  = threadIdx.x;
    const int warp = tid >> 5;
    const int lane = tid & 31;

    // ================= Phase A: row lifting in registers =================
    // Warp handles whole rows. Lane l owns pairs (64j+2l, 64j+2l+1), j=0..3 —
    // one coalesced float4 load each. Slot 1 == input row 2*r0-3 is never read
    // by Phase B when r0>0 (O rows start at slot 3), so skip it.
    for (int r = warp; r < nrows; r += 8) {
        if (r == 1 && r0 > 0) continue;    // dead halo row for interior strips
        const float4* __restrict__ xr =
            reinterpret_cast<const float4*>(xim + (size_t)r * Wd);
        float eA[4], oA[4], eB[4], oB[4];
        #pragma unroll
        for (int j = 0; j < 4; j++) {
            const float4 v = xr[32 * j + lane];
            eA[j] = v.x; oA[j] = v.y; eB[j] = v.z; oB[j] = v.w;
        }

        float dA[4], dB[4];
        #pragma unroll
        for (int j = 0; j < 4; j++) {
            float up = __shfl_up_sync(FULL, eB[j], 1);
            float cp = __shfl_sync(FULL, (j > 0) ? eB[j - 1] : eB[j], 31);
            float Eprev = (lane == 0) ? ((j == 0) ? eB[0] : cp) : up;   // refl i=0
            float dn = __shfl_down_sync(FULL, eA[j], 1);
            float cn = __shfl_sync(FULL, (j < 3) ? eA[j + 1] : eA[j], 0);
            float Enext = (lane == 31) ? ((j == 3) ? eA[3] : cn) : dn;  // refl i=255
            dA[j] = oA[j] - 0.5f * (Eprev + eB[j]);
            dB[j] = oB[j] - 0.5f * (eA[j] + Enext);
        }

        float* Arow = A + r * Wd;
        float2* __restrict__ srow = reinterpret_cast<float2*>(Arow);
        float2* __restrict__ drow = reinterpret_cast<float2*>(Arow + 256);
        #pragma unroll
        for (int j = 0; j < 4; j++) {
            float up = __shfl_up_sync(FULL, dB[j], 1);
            float cp = __shfl_sync(FULL, (j > 0) ? dB[j - 1] : dB[j], 31);
            float Dprev = (lane == 0) ? ((j == 0) ? dB[0] : cp) : up;
            float dn = __shfl_down_sync(FULL, dA[j], 1);
            float cn = __shfl_sync(FULL, (j < 3) ? dA[j + 1] : dA[j], 0);
            float Dnext = (lane == 31) ? ((j == 3) ? dA[3] : cn) : dn;
            float sA = eA[j] + 0.25f * (Dprev + dB[j]);
            float sB = eB[j] + 0.25f * (dA[j] + Dnext);
            srow[32 * j + lane] = make_float2(sA, sB);
            drow[32 * j + lane] = make_float2(dA[j], dB[j]);
        }
    }
    __syncthreads();

    // ============ Phase B: column lifting, 3-term sliding window ============
    // Thread owns a float2 column pair. t<128: s-columns (-> LL/LH);
    // t>=128: d-columns (-> HL/HH).
    {
        const int t  = tid;
        const int cc = (t & 127) * 2;                   // coefficient column (even)
        const int sb = (t < 128) ? 0 : 256;             // smem half offset

        auto ldrow = [&](int j) -> float2 {             // E[j] column pair
            return *reinterpret_cast<const float2*>(
                A + (2 * j - mlo) * Wd + sb + cc);
        };
        auto ldodd = [&](int j) -> float2 {             // O[j] column pair
            return *reinterpret_cast<const float2*>(
                A + (2 * j + 1 - mlo) * Wd + sb + cc);
        };

        const int b = bc >> 5;
        const int c = bc & 31;
        float* __restrict__ base = out + ((size_t)b * 128 + c) * 65536;
        float* __restrict__ sOut = base + ((t < 128) ? (size_t)0 : 64 * 65536);
        float* __restrict__ dOut = base + ((t < 128) ? 32 * 65536 : 96 * 65536);

        const int jstart = (r0 == 0)   ? 0   : (r0 - 1);
        const int jend   = (r0 == 248) ? 255 : (r0 + R);

        float2 eA = ldrow((r0 == 0) ? 1 : (r0 - 2));    // E[refl(jstart-1)]
        float2 eB = ldrow(jstart);                      // E[jstart]
        float2 Dm1 = make_float2(0.f, 0.f), Dm2 = make_float2(0.f, 0.f);

        for (int j = jstart; j <= jend; ++j) {
            const int jp = (j >= 255) ? 254 : (j + 1);
            const float2 eC = ldrow(jp);
            const float2 O  = ldodd(j);

            const float2 D = f2_fma(-0.5f, f2_add(eA, eC), O);

            if (j >= r0 && j <= r0 + R - 1) {
                __stcs(reinterpret_cast<float2*>(dOut + (size_t)j * 256 + cc), D);
            }
            if (j >= r0 + 1) {
                const float2 DA = (r0 == 0 && j == 1) ? D : Dm2;  // S[0] reflect
                const float2 S = f2_fma(0.25f, f2_add(DA, D), eA);
                __stcs(reinterpret_cast<float2*>(sOut + (size_t)(j - 1) * 256 + cc), S);
            }

            Dm2 = Dm1; Dm1 = D;
            eA = eB; eB = eC;
        }

        if (r0 == 248) {
            // S[255] = E[255] + 0.25*(2*D[254]); after final shift eA=E[255], Dm2=D[254]
            const float2 S = f2_fma(0.5f, Dm2, eA);
            __stcs(reinterpret_cast<float2*>(sOut + (size_t)255 * 256 + cc), S);
        }
    }
}

extern "C" void kernel_launch(void* const* d_in, const int* in_sizes, int n_in,
                              void* d_out, int out_size) {
    const float* x = (const float*)d_in[0];
    float* out = (float*)d_out;
    (void)in_sizes; (void)n_in; (void)out_size;

    static bool attr_set = false;
    if (!attr_set) {
        cudaFuncSetAttribute(lwt53_fused_kernel,
                             cudaFuncAttributeMaxDynamicSharedMemorySize, SMEM_BYTES);
        attr_set = true;
    }

    dim3 grid(NBC * NSTRIP);   // 8192
    dim3 block(256);
    lwt53_fused_kernel<<<grid, block, SMEM_BYTES>>>(x, out);
}